// round 3
// baseline (speedup 1.0000x reference)
#include <cuda_runtime.h>

#define L  4096
#define V  50257
#define H1 30
#define H2 50
#define G1 120   // 4*H1
#define G2 200   // 4*H2

// scratch (device globals: no allocation allowed)
__device__ float g_gx1[L * G1];
__device__ float g_h2 [L * H2];
__device__ float g_wf [G2 * H1];   // W_ih2 @ W1
__device__ float g_bf [G2];        // W_ih2 @ bl1 + b_ih2 + b_hh2

typedef unsigned long long u64;

__device__ __forceinline__ u64 pk2(float lo, float hi) {
    u64 r; asm("mov.b64 %0, {%1, %2};" : "=l"(r) : "f"(lo), "f"(hi)); return r;
}
__device__ __forceinline__ u64 ffma2(u64 a, u64 b, u64 c) {
    u64 d; asm("fma.rn.f32x2 %0, %1, %2, %3;" : "=l"(d) : "l"(a), "l"(b), "l"(c)); return d;
}
__device__ __forceinline__ u64 fadd2(u64 a, u64 b) {
    u64 d; asm("add.rn.f32x2 %0, %1, %2;" : "=l"(d) : "l"(a), "l"(b)); return d;
}
__device__ __forceinline__ float hsum2(u64 a) {
    float x, y; asm("mov.b64 {%0, %1}, %2;" : "=f"(x), "=f"(y) : "l"(a)); return x + y;
}

// accurate fast transcendentals (~2^-21 rel err)
__device__ __forceinline__ float fexp(float x) {
    float y; asm("ex2.approx.f32 %0, %1;" : "=f"(y) : "f"(x * 1.4426950408889634f)); return y;
}
__device__ __forceinline__ float frcp(float x) {
    float y; asm("rcp.approx.f32 %0, %1;" : "=f"(y) : "f"(x)); return y;
}
__device__ __forceinline__ float sigm(float x)   { return frcp(1.0f + fexp(-x)); }
__device__ __forceinline__ float tanh_f(float x) { return 1.0f - 2.0f * frcp(fexp(2.0f * x) + 1.0f); }

// packed dot of M u64-pairs with 4 accumulators
template<int M>
__device__ __forceinline__ float dotp(const u64* __restrict__ w, const u64* __restrict__ h) {
    u64 a0 = 0, a1 = 0, a2 = 0, a3 = 0;
#pragma unroll
    for (int m = 0; m < M; m += 4) a0 = ffma2(w[m], h[m], a0);
#pragma unroll
    for (int m = 1; m < M; m += 4) a1 = ffma2(w[m], h[m], a1);
#pragma unroll
    for (int m = 2; m < M; m += 4) a2 = ffma2(w[m], h[m], a2);
#pragma unroll
    for (int m = 3; m < M; m += 4) a3 = ffma2(w[m], h[m], a3);
    return hsum2(fadd2(fadd2(a0, a1), fadd2(a2, a3)));
}

// ---------------------------------------------------------------------------
// K1: gx1[t][j] = emb[x[t]] . w_ih1[j] + b_ih1[j] + b_hh1[j]
// ---------------------------------------------------------------------------
__global__ void k_gx1(const int* __restrict__ x, const float* __restrict__ emb,
                      const float* __restrict__ w_ih1, const float* __restrict__ b_ih1,
                      const float* __restrict__ b_hh1) {
    int idx = blockIdx.x * blockDim.x + threadIdx.x;
    if (idx >= L * G1) return;
    int t = idx / G1, j = idx % G1;
    const float* er = emb + (long)x[t] * H1;
    const float* wr = w_ih1 + j * H1;
    float s = b_ih1[j] + b_hh1[j];
#pragma unroll
    for (int k = 0; k < H1; k++) s += er[k] * wr[k];
    g_gx1[idx] = s;
}

// ---------------------------------------------------------------------------
// K2: fuse Wf = W_ih2 @ W1, bf = W_ih2 @ bl1 + b_ih2 + b_hh2
// ---------------------------------------------------------------------------
__global__ void k_fuse(const float* __restrict__ w_ih2, const float* __restrict__ w1,
                       const float* __restrict__ bl1, const float* __restrict__ b_ih2,
                       const float* __restrict__ b_hh2) {
    int idx = blockIdx.x * blockDim.x + threadIdx.x;
    if (idx < G2 * H1) {
        int j = idx / H1, m = idx % H1;
        float s = 0.0f;
#pragma unroll
        for (int k = 0; k < H2; k++) s += w_ih2[j * H2 + k] * w1[k * H1 + m];
        g_wf[idx] = s;
    }
    if (idx < G2) {
        float s = b_ih2[idx] + b_hh2[idx];
#pragma unroll
        for (int k = 0; k < H2; k++) s += w_ih2[idx * H2 + k] * bl1[k];
        g_bf[idx] = s;
    }
}

// ---------------------------------------------------------------------------
// K3: fused pipelined scan — layer1 (A), gx2 (B), layer2 (C) in one CTA.
// Iteration n: A does step n, B does step n-1, C does step n-2.
// ---------------------------------------------------------------------------
__global__ void __launch_bounds__(576, 1) k_scan(const float* __restrict__ w_hh1,
                                                 const float* __restrict__ w_hh2) {
    __shared__ __align__(16) float h1_sh[2][32];
    __shared__ __align__(16) float gx2_sh[2][G2];
    __shared__ __align__(16) float h2_sh[56];
    __shared__ float act1[G1];
    __shared__ float act2[G2];
    int tid = threadIdx.x;

    // group A: layer1 gate weights + gx1 prefetch
    u64 wa[H1 / 2];
    float gx_cur = 0.0f;
    if (tid < G1) {
        const float* w = w_hh1 + tid * H1;
#pragma unroll
        for (int m = 0; m < H1 / 2; m++) wa[m] = pk2(w[2 * m], w[2 * m + 1]);
        gx_cur = g_gx1[tid];
    }
    float c1 = 0.0f;

    // group B: fused Wf rows
    u64 wb[H1 / 2]; float bfv = 0.0f;
    if (tid >= 128 && tid < 128 + G2) {
        int j = tid - 128;
        const float* w = g_wf + j * H1;
#pragma unroll
        for (int m = 0; m < H1 / 2; m++) wb[m] = pk2(w[2 * m], w[2 * m + 1]);
        bfv = g_bf[j];
    }

    // group C: layer2 gate weights
    u64 wc[H2 / 2];
    if (tid >= 352 && tid < 352 + G2) {
        int j = tid - 352;
        const float* w = w_hh2 + j * H2;
#pragma unroll
        for (int m = 0; m < H2 / 2; m++) wc[m] = pk2(w[2 * m], w[2 * m + 1]);
    }
    float c2 = 0.0f;

    if (tid < 32) { h1_sh[0][tid] = 0.0f; h1_sh[1][tid] = 0.0f; }
    if (tid >= 64 && tid < 120) h2_sh[tid - 64] = 0.0f;
    __syncthreads();

    for (int n = 0; n < L + 2; n++) {
        // ---- phase 1: gates / gx2 ----
        if (tid < G1 && n < L) {
            float gx_next = (n + 1 < L) ? g_gx1[(n + 1) * G1 + tid] : 0.0f;
            const u64* hp = (const u64*)h1_sh[(n + 1) & 1];  // h1[n-1]
            float s = gx_cur + dotp<H1 / 2>(wa, hp);
            act1[tid] = (tid >= 2 * H1 && tid < 3 * H1) ? tanh_f(s) : sigm(s);
            gx_cur = gx_next;
        }
        if (tid >= 128 && tid < 128 + G2 && n >= 1 && n <= L) {
            const u64* hp = (const u64*)h1_sh[(n - 1) & 1];  // h1[n-1]
            gx2_sh[(n - 1) & 1][tid - 128] = bfv + dotp<H1 / 2>(wb, hp);
        }
        if (tid >= 352 && tid < 352 + G2 && n >= 2) {
            int j = tid - 352;
            const u64* hp = (const u64*)h2_sh;               // h2[n-3]
            float s = gx2_sh[n & 1][j] + dotp<H2 / 2>(wc, hp);
            act2[j] = (j >= 2 * H2 && j < 3 * H2) ? tanh_f(s) : sigm(s);
        }
        __syncthreads();
        // ---- phase 2: state updates ----
        if (tid < H1 && n < L) {
            float ai = act1[tid], af = act1[tid + H1];
            float ag = act1[tid + 2 * H1], ao = act1[tid + 3 * H1];
            c1 = af * c1 + ai * ag;
            h1_sh[n & 1][tid] = ao * tanh_f(c1);
        }
        if (tid >= 352 && tid < 352 + H2 && n >= 2) {
            int j = tid - 352;
            float ai = act2[j], af = act2[j + H2];
            float ag = act2[j + 2 * H2], ao = act2[j + 3 * H2];
            c2 = af * c2 + ai * ag;
            float h = ao * tanh_f(c2);
            h2_sh[j] = h;
            g_h2[(n - 2) * H2 + j] = h;
        }
        __syncthreads();
    }
}

// ---------------------------------------------------------------------------
// K4: out[t][v] = h2[t] . w2[v] + bl2[v]   (f32x2 packed FMA)
// ---------------------------------------------------------------------------
__global__ void k_out(const float* __restrict__ w2, const float* __restrict__ bl2,
                      float* __restrict__ out) {
    __shared__ __align__(16) float h_sh[32 * H2];
    int v = blockIdx.x * blockDim.x + threadIdx.x;
    bool active = (v < V);

    u64 wr[H2 / 2];
    float bias = 0.0f;
    if (active) {
        const float* w = w2 + (long)v * H2;
#pragma unroll
        for (int m = 0; m < H2 / 2; m++) wr[m] = pk2(w[2 * m], w[2 * m + 1]);
        bias = bl2[v];
    }

    int tbeg = blockIdx.y * (L / 4);
    int tend = tbeg + (L / 4);
    for (int t0 = tbeg; t0 < tend; t0 += 32) {
        __syncthreads();
        for (int i = threadIdx.x; i < 32 * H2; i += blockDim.x)
            h_sh[i] = g_h2[t0 * H2 + i];
        __syncthreads();
#pragma unroll 2
        for (int tt = 0; tt < 32; tt++) {
            const u64* hp = (const u64*)(h_sh + tt * H2);
            u64 a0 = 0, a1 = 0, a2 = 0, a3 = 0;
#pragma unroll
            for (int m = 0; m < H2 / 2; m += 4) a0 = ffma2(wr[m], hp[m], a0);
#pragma unroll
            for (int m = 1; m < H2 / 2; m += 4) a1 = ffma2(wr[m], hp[m], a1);
#pragma unroll
            for (int m = 2; m < H2 / 2; m += 4) a2 = ffma2(wr[m], hp[m], a2);
#pragma unroll
            for (int m = 3; m < H2 / 2; m += 4) a3 = ffma2(wr[m], hp[m], a3);
            if (active)
                out[(long)(t0 + tt) * V + v] =
                    hsum2(fadd2(fadd2(a0, a1), fadd2(a2, a3))) + bias;
        }
    }
}

// ---------------------------------------------------------------------------
extern "C" void kernel_launch(void* const* d_in, const int* in_sizes, int n_in,
                              void* d_out, int out_size) {
    const int*   x     = (const int*)  d_in[0];
    const float* emb   = (const float*)d_in[1];
    const float* w_ih1 = (const float*)d_in[2];
    const float* w_hh1 = (const float*)d_in[3];
    const float* b_ih1 = (const float*)d_in[4];
    const float* b_hh1 = (const float*)d_in[5];
    const float* w1    = (const float*)d_in[6];
    const float* bl1   = (const float*)d_in[7];
    const float* w_ih2 = (const float*)d_in[8];
    const float* w_hh2 = (const float*)d_in[9];
    const float* b_ih2 = (const float*)d_in[10];
    const float* b_hh2 = (const float*)d_in[11];
    const float* w2    = (const float*)d_in[12];
    const float* bl2   = (const float*)d_in[13];
    float* out = (float*)d_out;

    k_gx1 <<<(L * G1 + 255) / 256, 256>>>(x, emb, w_ih1, b_ih1, b_hh1);
    k_fuse<<<(G2 * H1 + 255) / 256, 256>>>(w_ih2, w1, bl1, b_ih2, b_hh2);
    k_scan<<<1, 576>>>(w_hh1, w_hh2);
    dim3 g5((V + 127) / 128, 4);
    k_out <<<g5, 128>>>(w2, bl2, out);
}

// round 4
// speedup vs baseline: 1.5273x; 1.5273x over previous
#include <cuda_runtime.h>

#define L  4096
#define V  50257
#define H1 30
#define H2 50
#define G1 120   // 4*H1
#define G2 200   // 4*H2

// scratch (device globals: no allocation allowed)
__device__ float g_gx1[L * G1];
__device__ float g_h2 [L * H2];
__device__ float g_wf [G2 * H1];   // W_ih2 @ W1
__device__ float g_bf [G2];        // W_ih2 @ bl1 + b_ih2 + b_hh2

typedef unsigned long long u64;

__device__ __forceinline__ u64 pk2(float lo, float hi) {
    u64 r; asm("mov.b64 %0, {%1, %2};" : "=l"(r) : "f"(lo), "f"(hi)); return r;
}
__device__ __forceinline__ u64 ffma2(u64 a, u64 b, u64 c) {
    u64 d; asm("fma.rn.f32x2 %0, %1, %2, %3;" : "=l"(d) : "l"(a), "l"(b), "l"(c)); return d;
}
__device__ __forceinline__ u64 fadd2(u64 a, u64 b) {
    u64 d; asm("add.rn.f32x2 %0, %1, %2;" : "=l"(d) : "l"(a), "l"(b)); return d;
}
__device__ __forceinline__ float hsum2(u64 a) {
    float x, y; asm("mov.b64 {%0, %1}, %2;" : "=f"(x), "=f"(y) : "l"(a)); return x + y;
}

// accurate fast transcendentals (~2^-21 rel err)
__device__ __forceinline__ float fexp(float x) {
    float y; asm("ex2.approx.f32 %0, %1;" : "=f"(y) : "f"(x * 1.4426950408889634f)); return y;
}
__device__ __forceinline__ float frcp(float x) {
    float y; asm("rcp.approx.f32 %0, %1;" : "=f"(y) : "f"(x)); return y;
}
__device__ __forceinline__ float sigm(float x)   { return frcp(1.0f + fexp(-x)); }
__device__ __forceinline__ float tanh_f(float x) { return 1.0f - 2.0f * frcp(fexp(2.0f * x) + 1.0f); }

// ---------------------------------------------------------------------------
// K1: gx1[t][j] = emb[x[t]] . w_ih1[j] + b_ih1[j] + b_hh1[j]
// ---------------------------------------------------------------------------
__global__ void k_gx1(const int* __restrict__ x, const float* __restrict__ emb,
                      const float* __restrict__ w_ih1, const float* __restrict__ b_ih1,
                      const float* __restrict__ b_hh1) {
    int idx = blockIdx.x * blockDim.x + threadIdx.x;
    if (idx >= L * G1) return;
    int t = idx / G1, j = idx % G1;
    const float* er = emb + (long)x[t] * H1;
    const float* wr = w_ih1 + j * H1;
    float s = b_ih1[j] + b_hh1[j];
#pragma unroll
    for (int k = 0; k < H1; k++) s += er[k] * wr[k];
    g_gx1[idx] = s;
}

// ---------------------------------------------------------------------------
// K2: fuse Wf = W_ih2 @ W1, bf = W_ih2 @ bl1 + b_ih2 + b_hh2
// ---------------------------------------------------------------------------
__global__ void k_fuse(const float* __restrict__ w_ih2, const float* __restrict__ w1,
                       const float* __restrict__ bl1, const float* __restrict__ b_ih2,
                       const float* __restrict__ b_hh2) {
    int idx = blockIdx.x * blockDim.x + threadIdx.x;
    if (idx < G2 * H1) {
        int j = idx / H1, m = idx % H1;
        float s = 0.0f;
#pragma unroll
        for (int k = 0; k < H2; k++) s += w_ih2[j * H2 + k] * w1[k * H1 + m];
        g_wf[idx] = s;
    }
    if (idx < G2) {
        float s = b_ih2[idx] + b_hh2[idx];
#pragma unroll
        for (int k = 0; k < H2; k++) s += w_ih2[idx * H2 + k] * bl1[k];
        g_bf[idx] = s;
    }
}

// ---------------------------------------------------------------------------
// K3: fused scan, 352 threads = 11 warps, ONE __syncthreads per step.
// Warp layout: lane = gate*8 + sub; warp owns 8 cells, all 4 gates in-warp,
// so the cell update uses 3 shfl.xor instead of a shared round-trip.
//   warps 0-3  : layer1 (cells wid*8+sub, valid < 30)
//   warps 4-10 : layer2 (cells (wid-4)*8+sub, valid < 50); each thread computes
//                gx2 (Wf.h1) AND the recurrent dot itself (no group B).
// Iteration n: layer1 produces h1[n]; layer2 produces h2[n-1] from h1[n-1].
// ---------------------------------------------------------------------------
__global__ void __launch_bounds__(352, 1) k_scan(const float* __restrict__ w_hh1,
                                                 const float* __restrict__ w_hh2) {
    __shared__ __align__(16) float h1_sh[2][32];   // 128B rows
    __shared__ __align__(16) float h2_sh[2][56];   // 224B rows (16B aligned)
    const int tid = threadIdx.x, wid = tid >> 5, lane = tid & 31;
    const int gate = lane >> 3, sub = lane & 7;
    const bool isA = (wid < 4);
    const int cell = isA ? wid * 8 + sub : (wid - 4) * 8 + sub;
    const bool valid = isA ? (cell < H1) : (cell < H2);

    u64 wa[15], wf[15], wc[25];
    float gx_cur = 0.0f, bfv = 0.0f;
    if (isA) {
#pragma unroll
        for (int m = 0; m < 15; m++) wa[m] = 0;
        if (valid) {
            const float* w = w_hh1 + (gate * H1 + cell) * H1;
#pragma unroll
            for (int m = 0; m < 15; m++) wa[m] = pk2(w[2 * m], w[2 * m + 1]);
            gx_cur = g_gx1[gate * H1 + cell];
        }
    } else {
#pragma unroll
        for (int m = 0; m < 15; m++) wf[m] = 0;
#pragma unroll
        for (int m = 0; m < 25; m++) wc[m] = 0;
        if (valid) {
            int j = gate * H2 + cell;
            const float* w = g_wf + j * H1;
#pragma unroll
            for (int m = 0; m < 15; m++) wf[m] = pk2(w[2 * m], w[2 * m + 1]);
            const float* w2r = w_hh2 + j * H2;
#pragma unroll
            for (int m = 0; m < 25; m++) wc[m] = pk2(w2r[2 * m], w2r[2 * m + 1]);
            bfv = g_bf[j];
        }
    }
    float c = 0.0f;
    if (tid < 32) { h1_sh[0][tid] = 0.0f; h1_sh[1][tid] = 0.0f; }
    if (tid >= 32 && tid < 88) { h2_sh[0][tid - 32] = 0.0f; h2_sh[1][tid - 32] = 0.0f; }
    __syncthreads();

    for (int n = 0; n <= L; n++) {
        if (isA) {
            if (n < L) {
                // prefetch next gx early (L2 latency covered by this step's work)
                float gx_next = 0.0f;
                if (valid && n + 1 < L) gx_next = g_gx1[(n + 1) * G1 + gate * H1 + cell];
                const u64* hq = (const u64*)h1_sh[(n + 1) & 1];      // h1[n-1]
                const ulonglong2* hv = (const ulonglong2*)hq;
                u64 a0 = 0, a1 = 0;
#pragma unroll
                for (int m = 0; m < 7; m++) {
                    ulonglong2 hh = hv[m];
                    a0 = ffma2(wa[2 * m],     hh.x, a0);
                    a1 = ffma2(wa[2 * m + 1], hh.y, a1);
                }
                a0 = ffma2(wa[14], hq[14], a0);
                float s = gx_cur + hsum2(fadd2(a0, a1));
                float act = (gate == 2) ? tanh_f(s) : sigm(s);
                float y1 = __shfl_xor_sync(0xffffffffu, act, 8);
                float y2 = __shfl_xor_sync(0xffffffffu, act, 16);
                float y3 = __shfl_xor_sync(0xffffffffu, act, 24);
                float ai, af, ag, ao;
                if      (gate == 0) { ai = act; af = y1;  ag = y2;  ao = y3;  }
                else if (gate == 1) { ai = y1;  af = act; ag = y3;  ao = y2;  }
                else if (gate == 2) { ai = y2;  af = y3;  ag = act; ao = y1;  }
                else                { ai = y3;  af = y2;  ag = y1;  ao = act; }
                c = af * c + ai * ag;
                float h = ao * tanh_f(c);
                if (gate == 0 && valid) h1_sh[n & 1][cell] = h;
                gx_cur = gx_next;
            }
        } else if (n >= 1) {
            const u64* hq1 = (const u64*)h1_sh[(n - 1) & 1];          // h1[n-1]
            const u64* hq2 = (const u64*)h2_sh[n & 1];                // h2[n-2]
            const ulonglong2* hv1 = (const ulonglong2*)hq1;
            const ulonglong2* hv2 = (const ulonglong2*)hq2;
            u64 a0 = 0, a1 = 0, a2 = 0, a3 = 0;
#pragma unroll
            for (int m = 0; m < 7; m++) {
                ulonglong2 hh = hv1[m];
                a0 = ffma2(wf[2 * m],     hh.x, a0);
                a1 = ffma2(wf[2 * m + 1], hh.y, a1);
            }
            a0 = ffma2(wf[14], hq1[14], a0);
#pragma unroll
            for (int m = 0; m < 12; m++) {
                ulonglong2 hh = hv2[m];
                a2 = ffma2(wc[2 * m],     hh.x, a2);
                a3 = ffma2(wc[2 * m + 1], hh.y, a3);
            }
            a2 = ffma2(wc[24], hq2[24], a2);
            float s = bfv + hsum2(fadd2(fadd2(a0, a1), fadd2(a2, a3)));
            float act = (gate == 2) ? tanh_f(s) : sigm(s);
            float y1 = __shfl_xor_sync(0xffffffffu, act, 8);
            float y2 = __shfl_xor_sync(0xffffffffu, act, 16);
            float y3 = __shfl_xor_sync(0xffffffffu, act, 24);
            float ai, af, ag, ao;
            if      (gate == 0) { ai = act; af = y1;  ag = y2;  ao = y3;  }
            else if (gate == 1) { ai = y1;  af = act; ag = y3;  ao = y2;  }
            else if (gate == 2) { ai = y2;  af = y3;  ag = act; ao = y1;  }
            else                { ai = y3;  af = y2;  ag = y1;  ao = act; }
            c = af * c + ai * ag;
            float h = ao * tanh_f(c);
            if (gate == 0 && valid) {
                h2_sh[(n - 1) & 1][cell] = h;
                g_h2[(n - 1) * H2 + cell] = h;
            }
        }
        __syncthreads();
    }
}

// ---------------------------------------------------------------------------
// K4: out[t][v] = h2[t] . w2[v] + bl2[v]  (f32x2 FMA, LDS.128 h-tile)
// grid: (ceil(V/128), 8); each y-slice handles 512 timesteps
// ---------------------------------------------------------------------------
__global__ void k_out(const float* __restrict__ w2, const float* __restrict__ bl2,
                      float* __restrict__ out) {
    __shared__ __align__(16) float h_sh[32 * 56];   // padded rows: 224B, 16B aligned
    int v = blockIdx.x * blockDim.x + threadIdx.x;
    bool active = (v < V);

    u64 wr[25];
    float bias = 0.0f;
    if (active) {
        const float* w = w2 + (long)v * H2;
#pragma unroll
        for (int m = 0; m < 25; m++) wr[m] = pk2(w[2 * m], w[2 * m + 1]);
        bias = bl2[v];
    }

    int tbeg = blockIdx.y * (L / 8);
    int tend = tbeg + (L / 8);
    for (int t0 = tbeg; t0 < tend; t0 += 32) {
        __syncthreads();
        for (int i = threadIdx.x; i < 32 * H2; i += blockDim.x) {
            int r = i / H2, col = i - r * H2;
            h_sh[r * 56 + col] = g_h2[(t0 + r) * H2 + i - r * H2 + 0 * col];
        }
        __syncthreads();
#pragma unroll 4
        for (int tt = 0; tt < 32; tt++) {
            const u64* hq = (const u64*)(h_sh + tt * 56);
            const ulonglong2* hv = (const ulonglong2*)hq;
            u64 a0 = 0, a1 = 0, a2 = 0, a3 = 0;
#pragma unroll
            for (int m = 0; m < 6; m++) {
                ulonglong2 hh = hv[2 * m];
                a0 = ffma2(wr[4 * m],     hh.x, a0);
                a1 = ffma2(wr[4 * m + 1], hh.y, a1);
                ulonglong2 hh2 = hv[2 * m + 1];
                a2 = ffma2(wr[4 * m + 2], hh2.x, a2);
                a3 = ffma2(wr[4 * m + 3], hh2.y, a3);
            }
            a0 = ffma2(wr[24], hq[24], a0);
            if (active)
                out[(long)(t0 + tt) * V + v] =
                    hsum2(fadd2(fadd2(a0, a1), fadd2(a2, a3))) + bias;
        }
    }
}

// ---------------------------------------------------------------------------
extern "C" void kernel_launch(void* const* d_in, const int* in_sizes, int n_in,
                              void* d_out, int out_size) {
    const int*   x     = (const int*)  d_in[0];
    const float* emb   = (const float*)d_in[1];
    const float* w_ih1 = (const float*)d_in[2];
    const float* w_hh1 = (const float*)d_in[3];
    const float* b_ih1 = (const float*)d_in[4];
    const float* b_hh1 = (const float*)d_in[5];
    const float* w1    = (const float*)d_in[6];
    const float* bl1   = (const float*)d_in[7];
    const float* w_ih2 = (const float*)d_in[8];
    const float* w_hh2 = (const float*)d_in[9];
    const float* b_ih2 = (const float*)d_in[10];
    const float* b_hh2 = (const float*)d_in[11];
    const float* w2    = (const float*)d_in[12];
    const float* bl2   = (const float*)d_in[13];
    float* out = (float*)d_out;

    k_gx1 <<<(L * G1 + 255) / 256, 256>>>(x, emb, w_ih1, b_ih1, b_hh1);
    k_fuse<<<(G2 * H1 + 255) / 256, 256>>>(w_ih2, w1, bl1, b_ih2, b_hh2);
    k_scan<<<1, 352>>>(w_hh1, w_hh2);
    dim3 g5((V + 127) / 128, 8);
    k_out <<<g5, 128>>>(w2, bl2, out);
}

// round 6
// speedup vs baseline: 1.5448x; 1.0115x over previous
#include <cuda_runtime.h>

#define L  4096
#define V  50257
#define H1 30
#define H2 50
#define G1 120   // 4*H1
#define G2 200   // 4*H2

// scratch (device globals: no allocation allowed)
__device__ float g_gx1p[L * 128];   // [t][cell*4 + gate], row padded to 128
__device__ float g_h1r [L * 32];    // layer1 hidden ring, row padded to 32
__device__ float g_h2  [L * H2];
__device__ float g_wf  [G2 * H1];   // W_ih2 @ W1
__device__ float g_bf  [G2];        // W_ih2 @ bl1 + b_ih2 + b_hh2
__device__ int   g_prog;            // #steps of h1 published

typedef unsigned long long u64;

__device__ __forceinline__ u64 pk2(float lo, float hi) {
    u64 r; asm("mov.b64 %0, {%1, %2};" : "=l"(r) : "f"(lo), "f"(hi)); return r;
}
__device__ __forceinline__ u64 ffma2(u64 a, u64 b, u64 c) {
    u64 d; asm("fma.rn.f32x2 %0, %1, %2, %3;" : "=l"(d) : "l"(a), "l"(b), "l"(c)); return d;
}
__device__ __forceinline__ u64 fadd2(u64 a, u64 b) {
    u64 d; asm("add.rn.f32x2 %0, %1, %2;" : "=l"(d) : "l"(a), "l"(b)); return d;
}
__device__ __forceinline__ float hsum2(u64 a) {
    float x, y; asm("mov.b64 {%0, %1}, %2;" : "=f"(x), "=f"(y) : "l"(a)); return x + y;
}

__device__ __forceinline__ float fexp(float x) {
    float y; asm("ex2.approx.f32 %0, %1;" : "=f"(y) : "f"(x * 1.4426950408889634f)); return y;
}
__device__ __forceinline__ float frcp(float x) {
    float y; asm("rcp.approx.f32 %0, %1;" : "=f"(y) : "f"(x)); return y;
}
__device__ __forceinline__ float sigm(float x)   { return frcp(1.0f + fexp(-x)); }
__device__ __forceinline__ float tanh_f(float x) { return 1.0f - 2.0f * frcp(fexp(2.0f * x) + 1.0f); }

// ---------------------------------------------------------------------------
// K1: gx1p[t][c*4+g] = emb[x[t]] . w_ih1[g*30+c] + b_ih1 + b_hh1 (pad -> 0)
// Also resets the progress flag.
// ---------------------------------------------------------------------------
__global__ void k_gx1(const int* __restrict__ x, const float* __restrict__ emb,
                      const float* __restrict__ w_ih1, const float* __restrict__ b_ih1,
                      const float* __restrict__ b_hh1) {
    int idx = blockIdx.x * blockDim.x + threadIdx.x;
    if (idx == 0) g_prog = 0;
    if (idx >= L * 128) return;
    int t = idx >> 7, jj = idx & 127;
    int c = jj >> 2, g = jj & 3;
    float s = 0.0f;
    if (c < H1) {
        int j = g * H1 + c;
        const float* er = emb + (long)x[t] * H1;
        const float* wr = w_ih1 + j * H1;
        s = b_ih1[j] + b_hh1[j];
#pragma unroll
        for (int k = 0; k < H1; k++) s += er[k] * wr[k];
    }
    g_gx1p[idx] = s;
}

// ---------------------------------------------------------------------------
// K2: fuse Wf = W_ih2 @ W1, bf = W_ih2 @ bl1 + b_ih2 + b_hh2
// ---------------------------------------------------------------------------
__global__ void k_fuse(const float* __restrict__ w_ih2, const float* __restrict__ w1,
                       const float* __restrict__ bl1, const float* __restrict__ b_ih2,
                       const float* __restrict__ b_hh2) {
    int idx = blockIdx.x * blockDim.x + threadIdx.x;
    if (idx < G2 * H1) {
        int j = idx / H1, m = idx % H1;
        float s = 0.0f;
#pragma unroll
        for (int k = 0; k < H2; k++) s += w_ih2[j * H2 + k] * w1[k * H1 + m];
        g_wf[idx] = s;
    }
    if (idx < G2) {
        float s = b_ih2[idx] + b_hh2[idx];
#pragma unroll
        for (int k = 0; k < H2; k++) s += w_ih2[idx] * 0.0f + w_ih2[idx * H2 + k] * bl1[k];
        g_bf[idx] = s;
    }
}

// ---------------------------------------------------------------------------
// K3: two cooperating CTAs on two SMs.
//   blockIdx.x == 1 : layer1 — ONE warp, lane=cell, all 4 gates in-lane,
//                     no barriers; publishes h1 ring + release flag / 8 steps.
//   blockIdx.x == 0 : layer2 — warps 0-6 gates (R3 layout), warp 7 prefetches
//                     h1[n+1] from the ring (acquire flag), 1 barrier/step.
// ---------------------------------------------------------------------------
__global__ void __launch_bounds__(256, 1) k_scan(const float* __restrict__ w_hh1,
                                                 const float* __restrict__ w_hh2) {
    const int tid = threadIdx.x, wid = tid >> 5, lane = tid & 31;

    if (blockIdx.x == 1) {
        // ================= layer 1 : single warp =================
        if (wid != 0) return;
        __shared__ __align__(16) float h_sh[32];
        const int c = lane;
        const bool valid = (c < H1);

        u64 w[4][15];
#pragma unroll
        for (int g = 0; g < 4; g++)
#pragma unroll
            for (int m = 0; m < 15; m++) w[g][m] = 0;
        if (valid) {
#pragma unroll
            for (int g = 0; g < 4; g++) {
                const float* row = w_hh1 + (g * H1 + c) * H1;
#pragma unroll
                for (int m = 0; m < 15; m++) w[g][m] = pk2(row[2 * m], row[2 * m + 1]);
            }
        }
        h_sh[lane] = 0.0f;
        __syncwarp();

        float cst = 0.0f;
        float4 gxbuf[2];
        gxbuf[0] = __ldg((const float4*)&g_gx1p[0 * 128 + c * 4]);
        gxbuf[1] = __ldg((const float4*)&g_gx1p[1 * 128 + c * 4]);

        for (int n = 0; n < L; n++) {
            float4 gx = gxbuf[n & 1];
            if (n + 2 < L)
                gxbuf[n & 1] = __ldg((const float4*)&g_gx1p[(n + 2) * 128 + c * 4]);

            const u64* hp = (const u64*)h_sh;
            u64 hv[15];
            {
                const ulonglong2* h2p = (const ulonglong2*)h_sh;
#pragma unroll
                for (int m = 0; m < 7; m++) { ulonglong2 t2 = h2p[m]; hv[2*m] = t2.x; hv[2*m+1] = t2.y; }
                hv[14] = hp[14];
            }
            u64 a0[4], a1[4];
#pragma unroll
            for (int g = 0; g < 4; g++) { a0[g] = 0; a1[g] = 0; }
#pragma unroll
            for (int g = 0; g < 4; g++) {
#pragma unroll
                for (int m = 0; m < 15; m += 2) a0[g] = ffma2(w[g][m], hv[m], a0[g]);
#pragma unroll
                for (int m = 1; m < 15; m += 2) a1[g] = ffma2(w[g][m], hv[m], a1[g]);
            }
            float si = gx.x + hsum2(fadd2(a0[0], a1[0]));
            float sf = gx.y + hsum2(fadd2(a0[1], a1[1]));
            float sg = gx.z + hsum2(fadd2(a0[2], a1[2]));
            float so = gx.w + hsum2(fadd2(a0[3], a1[3]));
            float ai = sigm(si), af = sigm(sf), ag = tanh_f(sg), ao = sigm(so);
            cst = af * cst + ai * ag;
            float h = valid ? ao * tanh_f(cst) : 0.0f;
            __syncwarp();
            h_sh[lane] = h;
            g_h1r[n * 32 + lane] = h;
            __syncwarp();
            if ((n & 7) == 7) {
                __threadfence();
                if (lane == 0) {
                    int val = n + 1;
                    asm volatile("st.global.release.gpu.s32 [%0], %1;"
                                 :: "l"(&g_prog), "r"(val) : "memory");
                }
            }
        }
        return;
    }

    // ================= layer 2 : 8 warps =================
    __shared__ __align__(16) float h1s[2][32];
    __shared__ __align__(16) float h2s[2][56];
    const int gate = lane >> 3, sub = lane & 7;
    const bool isGate = (wid < 7);
    const int cell = wid * 8 + sub;
    const bool valid = isGate && (cell < H2);

    u64 wf[15], wc[25];
    float bfv = 0.0f;
#pragma unroll
    for (int m = 0; m < 15; m++) wf[m] = 0;
#pragma unroll
    for (int m = 0; m < 25; m++) wc[m] = 0;
    if (valid) {
        int j = gate * H2 + cell;
        const float* w = g_wf + j * H1;
#pragma unroll
        for (int m = 0; m < 15; m++) wf[m] = pk2(w[2 * m], w[2 * m + 1]);
        const float* w2r = w_hh2 + j * H2;
#pragma unroll
        for (int m = 0; m < 25; m++) wc[m] = pk2(w2r[2 * m], w2r[2 * m + 1]);
        bfv = g_bf[j];
    }
    if (tid < 56) { h2s[0][tid] = 0.0f; h2s[1][tid] = 0.0f; }

    int seen = 0;  // spare-warp lane 0's cached view of g_prog
    if (wid == 7) {
        if (lane == 0) {
            do { asm volatile("ld.global.acquire.gpu.s32 %0, [%1];"
                              : "=r"(seen) : "l"(&g_prog) : "memory"); } while (seen < 1);
        }
        __syncwarp();
        if (lane < 8)
            ((float4*)h1s[0])[lane] = __ldg((const float4*)&g_h1r[0 * 32 + lane * 4]);
    }
    __syncthreads();

    float cst = 0.0f;
    for (int n = 0; n < L; n++) {
        if (isGate) {
            const u64* hq1 = (const u64*)h1s[n & 1];
            const u64* hq2 = (const u64*)h2s[n & 1];
            const ulonglong2* hv1 = (const ulonglong2*)hq1;
            const ulonglong2* hv2 = (const ulonglong2*)hq2;
            u64 a0 = 0, a1 = 0, a2 = 0, a3 = 0;
#pragma unroll
            for (int m = 0; m < 7; m++) {
                ulonglong2 hh = hv1[m];
                a0 = ffma2(wf[2 * m],     hh.x, a0);
                a1 = ffma2(wf[2 * m + 1], hh.y, a1);
            }
            a0 = ffma2(wf[14], hq1[14], a0);
#pragma unroll
            for (int m = 0; m < 12; m++) {
                ulonglong2 hh = hv2[m];
                a2 = ffma2(wc[2 * m],     hh.x, a2);
                a3 = ffma2(wc[2 * m + 1], hh.y, a3);
            }
            a2 = ffma2(wc[24], hq2[24], a2);
            float s = bfv + hsum2(fadd2(fadd2(a0, a1), fadd2(a2, a3)));
            float act = (gate == 2) ? tanh_f(s) : sigm(s);
            float y1 = __shfl_xor_sync(0xffffffffu, act, 8);
            float y2 = __shfl_xor_sync(0xffffffffu, act, 16);
            float y3 = __shfl_xor_sync(0xffffffffu, act, 24);
            float ai, af, ag, ao;
            if      (gate == 0) { ai = act; af = y1;  ag = y2;  ao = y3;  }
            else if (gate == 1) { ai = y1;  af = act; ag = y3;  ao = y2;  }
            else if (gate == 2) { ai = y2;  af = y3;  ag = act; ao = y1;  }
            else                { ai = y3;  af = y2;  ag = y1;  ao = act; }
            cst = af * cst + ai * ag;
            float h = ao * tanh_f(cst);
            if (gate == 0 && valid) {
                h2s[(n + 1) & 1][cell] = h;
                g_h2[n * H2 + cell] = h;
            }
        } else {
            // warp 7: prefetch h1[n+1]
            int np1 = n + 1;
            if (np1 < L) {
                if (lane == 0 && seen < np1 + 1) {
                    do { asm volatile("ld.global.acquire.gpu.s32 %0, [%1];"
                                      : "=r"(seen) : "l"(&g_prog) : "memory"); } while (seen < np1 + 1);
                }
                __syncwarp();
                if (lane < 8)
                    ((float4*)h1s[np1 & 1])[lane] =
                        __ldg((const float4*)&g_h1r[np1 * 32 + lane * 4]);
            }
        }
        __syncthreads();
    }
}

// ---------------------------------------------------------------------------
// K4: out[t][v] = h2[t] . w2[v] + bl2[v]  (f32x2 FMA, LDS.128 h-tile)
// grid: (ceil(V/128), 16); each y-slice handles 256 timesteps
// ---------------------------------------------------------------------------
__global__ void k_out(const float* __restrict__ w2, const float* __restrict__ bl2,
                      float* __restrict__ out) {
    __shared__ __align__(16) float h_sh[32 * 56];
    int v = blockIdx.x * blockDim.x + threadIdx.x;
    bool active = (v < V);

    u64 wr[25];
    float bias = 0.0f;
    if (active) {
        const float* w = w2 + (long)v * H2;
#pragma unroll
        for (int m = 0; m < 25; m++) wr[m] = pk2(w[2 * m], w[2 * m + 1]);
        bias = bl2[v];
    }

    int tbeg = blockIdx.y * (L / 16);
    int tend = tbeg + (L / 16);
    for (int t0 = tbeg; t0 < tend; t0 += 32) {
        __syncthreads();
        for (int i = threadIdx.x; i < 32 * H2; i += blockDim.x) {
            int r = i / H2, col = i - r * H2;
            h_sh[r * 56 + col] = g_h2[(t0 + r) * H2 + col];
        }
        __syncthreads();
#pragma unroll 4
        for (int tt = 0; tt < 32; tt++) {
            const u64* hq = (const u64*)(h_sh + tt * 56);
            const ulonglong2* hv = (const ulonglong2*)hq;
            u64 a0 = 0, a1 = 0, a2 = 0, a3 = 0;
#pragma unroll
            for (int m = 0; m < 6; m++) {
                ulonglong2 hh = hv[2 * m];
                a0 = ffma2(wr[4 * m],     hh.x, a0);
                a1 = ffma2(wr[4 * m + 1], hh.y, a1);
                ulonglong2 hh2 = hv[2 * m + 1];
                a2 = ffma2(wr[4 * m + 2], hh2.x, a2);
                a3 = ffma2(wr[4 * m + 3], hh2.y, a3);
            }
            a0 = ffma2(wr[24], hq[24], a0);
            if (active)
                out[(long)(t0 + tt) * V + v] =
                    hsum2(fadd2(fadd2(a0, a1), fadd2(a2, a3))) + bias;
        }
    }
}

// ---------------------------------------------------------------------------
extern "C" void kernel_launch(void* const* d_in, const int* in_sizes, int n_in,
                              void* d_out, int out_size) {
    const int*   x     = (const int*)  d_in[0];
    const float* emb   = (const float*)d_in[1];
    const float* w_ih1 = (const float*)d_in[2];
    const float* w_hh1 = (const float*)d_in[3];
    const float* b_ih1 = (const float*)d_in[4];
    const float* b_hh1 = (const float*)d_in[5];
    const float* w1    = (const float*)d_in[6];
    const float* bl1   = (const float*)d_in[7];
    const float* w_ih2 = (const float*)d_in[8];
    const float* w_hh2 = (const float*)d_in[9];
    const float* b_ih2 = (const float*)d_in[10];
    const float* b_hh2 = (const float*)d_in[11];
    const float* w2    = (const float*)d_in[12];
    const float* bl2   = (const float*)d_in[13];
    float* out = (float*)d_out;

    k_gx1 <<<(L * 128 + 255) / 256, 256>>>(x, emb, w_ih1, b_ih1, b_hh1);
    k_fuse<<<(G2 * H1 + 255) / 256, 256>>>(w_ih2, w1, bl1, b_ih2, b_hh2);
    k_scan<<<2, 256>>>(w_hh1, w_hh2);
    dim3 g5((V + 127) / 128, 16);
    k_out <<<g5, 128>>>(w2, bl2, out);
}